// round 14
// baseline (speedup 1.0000x reference)
#include <cuda_runtime.h>
#include <math.h>

// ---------------- global scratch (no allocations allowed) ----------------
__device__ float q_g[4 * 1024 * 8];
__device__ float k_g[4 * 1024 * 8];
__device__ float v_g[4 * 1024 * 8];

typedef unsigned long long u64;

__device__ __forceinline__ float tanh_f(float x) {
    float y; asm("tanh.approx.f32 %0, %1;" : "=f"(y) : "f"(x)); return y;
}
__device__ __forceinline__ float sigf(float x) {
    return fmaf(0.5f, tanh_f(0.5f * x), 0.5f);
}
__device__ __forceinline__ u64 pack2(float a, float b) {
    u64 r; asm("mov.b64 %0, {%1,%2};" : "=l"(r) : "f"(a), "f"(b)); return r;
}
__device__ __forceinline__ void unpack2(u64 v, float& a, float& b) {
    asm("mov.b64 {%0,%1}, %2;" : "=f"(a), "=f"(b) : "l"(v));
}
__device__ __forceinline__ u64 fma2(u64 a, u64 b, u64 c) {
    u64 d; asm("fma.rn.f32x2 %0, %1, %2, %3;" : "=l"(d) : "l"(a), "l"(b), "l"(c)); return d;
}
__device__ __forceinline__ u64 add2(u64 a, u64 b) {
    u64 d; asm("add.rn.f32x2 %0, %1, %2;" : "=l"(d) : "l"(a), "l"(b)); return d;
}

// =====================================================================
// Kernel 1: pipelined LSTM1 + LSTM2, balanced 16-iter GEMVs.
//   (byte-identical to the round-13 best)
// =====================================================================
__global__ void __launch_bounds__(896, 1) lstm_kernel(
    const float* __restrict__ x,
    const float* __restrict__ emb_w, const float* __restrict__ emb_b,
    const float* __restrict__ w1, const float* __restrict__ u1,
    const float* __restrict__ b1i, const float* __restrict__ b1h,
    const float* __restrict__ w2, const float* __restrict__ u2,
    const float* __restrict__ b2i, const float* __restrict__ b2h,
    const float* __restrict__ attn_w, const float* __restrict__ attn_b)
{
    extern __shared__ __align__(16) float sm[];
    float* g1p    = sm;              // [4][8][256]  8192
    float* g2p    = g1p + 8192;     // [6][8][128]  6144
    float* pt1s   = g2p + 6144;     // [16][256]    4096
    float* pe     = pt1s + 4096;    // [16][32]      512
    float* xs     = pe + 512;       // [16][8]       128
    float* hcat   = xs + 128;       // [2][96][8]   1536
    float* embw_s = hcat + 1536;    // 32
    float* embb_s = embw_s + 32;    // 32

    const int tid = threadIdx.x;
    const int b0 = blockIdx.x * 8;

    // ---- shared prologue ----
    if (tid < 512) {
        int t = tid >> 5, e = tid & 31;
        int half = e >> 1;
        float div = __expf(-(float)(2 * half) * (9.210340371976184f / 32.0f));
        float arg = (float)t * div;
        pe[tid] = (e & 1) ? __cosf(arg) : __sinf(arg);
    }
    if (tid < 32) { embw_s[tid] = emb_w[tid]; embb_s[tid] = emb_b[tid]; }
    if (tid < 128) { int t = tid >> 3, b = tid & 7; xs[tid] = x[(b0 + b) * 16 + t]; }
    for (int i = tid; i < 1536; i += 896) hcat[i] = 0.f;
    __syncthreads();

    // ---- pt1s + we1 (embedding folded into LSTM1): threads < 256 ----
    if (tid < 256) {
        int gate = 2 * (tid & 127) + (tid >> 7);
        float w1r[32];
        const float4* w1p = (const float4*)(w1 + gate * 32);
        #pragma unroll
        for (int qq = 0; qq < 8; qq++) {
            float4 v = w1p[qq];
            w1r[qq*4+0]=v.x; w1r[qq*4+1]=v.y; w1r[qq*4+2]=v.z; w1r[qq*4+3]=v.w;
        }
        float we1 = 0.f, wb = b1i[gate] + b1h[gate];
        #pragma unroll
        for (int e = 0; e < 32; e++) {
            we1 = fmaf(w1r[e], embw_s[e], we1);
            wb  = fmaf(w1r[e], embb_s[e], wb);
        }
        g1p[gate] = we1;   // stash
        #pragma unroll
        for (int t = 0; t < 16; t++) {
            float s = wb;
            #pragma unroll
            for (int e = 0; e < 32; e++) s = fmaf(w1r[e], pe[t * 32 + e], s);
            pt1s[t * 256 + gate] = s;
        }
    }
    __syncthreads();

    // ---- per-thread register setup ----
    float wreg[32];
    u64 weA = 0, weB = 0, bvA = 0, bvB = 0;
    float c1r = 0.f, c2r = 0.f;
    int pA = 0, qA = 0, pB = 0, sB = 0;

    if (tid < 512) {
        pA = tid & 127; qA = tid >> 7;
        const float4* a0 = (const float4*)(u1 + (2 * pA) * 64 + qA * 16);
        const float4* a1 = (const float4*)(u1 + (2 * pA + 1) * 64 + qA * 16);
        #pragma unroll
        for (int qq = 0; qq < 4; qq++) {
            float4 v = a0[qq];
            wreg[qq*4+0]=v.x; wreg[qq*4+1]=v.y; wreg[qq*4+2]=v.z; wreg[qq*4+3]=v.w;
            float4 u = a1[qq];
            wreg[16+qq*4+0]=u.x; wreg[16+qq*4+1]=u.y; wreg[16+qq*4+2]=u.z; wreg[16+qq*4+3]=u.w;
        }
        if (qA == 0) {
            float wa = g1p[2 * pA], wbv = g1p[2 * pA + 1];
            weA = pack2(wa, wa); weB = pack2(wbv, wbv);
        }
    } else {
        int t2 = tid - 512;
        pB = t2 & 63; sB = t2 >> 6;   // sB in [0,6)
        #pragma unroll
        for (int g = 0; g < 2; g++) {
            int row = 2 * pB + g;
            const float4* p = (sB < 4)
                ? (const float4*)(w2 + row * 64 + sB * 16)
                : (const float4*)(u2 + row * 32 + (sB - 4) * 16);
            #pragma unroll
            for (int qq = 0; qq < 4; qq++) {
                float4 v = p[qq];
                wreg[g*16+qq*4+0]=v.x; wreg[g*16+qq*4+1]=v.y;
                wreg[g*16+qq*4+2]=v.z; wreg[g*16+qq*4+3]=v.w;
            }
        }
        if (sB == 0) {
            float ba = b2i[2 * pB] + b2h[2 * pB];
            float bb = b2i[2 * pB + 1] + b2h[2 * pB + 1];
            bvA = pack2(ba, ba); bvB = pack2(bb, bb);
        }
    }
    __syncthreads();   // stash in g1p consumed before main loop overwrites

    // ---- pipelined main loop: 17 iterations ----
    for (int i = 0; i < 17; ++i) {
        int cur = i & 1;
        const float* hc = hcat + cur * 768;
        float* hn = hcat + (cur ^ 1) * 768;
        if (tid < 512) {
            if (i < 16) {
                u64 a00, a01, a02, a03, a10, a11, a12, a13;
                if (qA == 0) {
                    float pt0 = pt1s[i * 256 + 2 * pA];
                    float pt1 = pt1s[i * 256 + 2 * pA + 1];
                    u64 p0 = pack2(pt0, pt0), p1 = pack2(pt1, pt1);
                    const ulonglong2* xp = (const ulonglong2*)&xs[i * 8];
                    ulonglong2 x01 = xp[0], x23 = xp[1];
                    a00 = fma2(weA, x01.x, p0); a01 = fma2(weA, x01.y, p0);
                    a02 = fma2(weA, x23.x, p0); a03 = fma2(weA, x23.y, p0);
                    a10 = fma2(weB, x01.x, p1); a11 = fma2(weB, x01.y, p1);
                    a12 = fma2(weB, x23.x, p1); a13 = fma2(weB, x23.y, p1);
                } else {
                    a00=a01=a02=a03=a10=a11=a12=a13=0ULL;
                }
                const float* hk = hc + qA * 128;
                #pragma unroll
                for (int k = 0; k < 16; k++) {
                    ulonglong2 hA = *(const ulonglong2*)&hk[k * 8];
                    ulonglong2 hB = *(const ulonglong2*)&hk[k * 8 + 4];
                    u64 w0 = pack2(wreg[k], wreg[k]);
                    a00 = fma2(w0, hA.x, a00); a01 = fma2(w0, hA.y, a01);
                    a02 = fma2(w0, hB.x, a02); a03 = fma2(w0, hB.y, a03);
                    u64 w1p = pack2(wreg[16 + k], wreg[16 + k]);
                    a10 = fma2(w1p, hA.x, a10); a11 = fma2(w1p, hA.y, a11);
                    a12 = fma2(w1p, hB.x, a12); a13 = fma2(w1p, hB.y, a13);
                }
                float f0, f1;
                float* gp0 = g1p + qA * 2048 + 2 * pA;
                unpack2(a00, f0, f1); gp0[0]    = f0; gp0[256]  = f1;
                unpack2(a01, f0, f1); gp0[512]  = f0; gp0[768]  = f1;
                unpack2(a02, f0, f1); gp0[1024] = f0; gp0[1280] = f1;
                unpack2(a03, f0, f1); gp0[1536] = f0; gp0[1792] = f1;
                float* gp1 = gp0 + 1;
                unpack2(a10, f0, f1); gp1[0]    = f0; gp1[256]  = f1;
                unpack2(a11, f0, f1); gp1[512]  = f0; gp1[768]  = f1;
                unpack2(a12, f0, f1); gp1[1024] = f0; gp1[1280] = f1;
                unpack2(a13, f0, f1); gp1[1536] = f0; gp1[1792] = f1;

                asm volatile("bar.sync 1, 512;" ::: "memory");

                // cell update: one cell per thread, sum 4 quarters
                int b = tid >> 6, j = tid & 63;
                const float* gp = g1p + b * 256 + j;
                float gi = gp[0]       + gp[2048]      + gp[4096]      + gp[6144];
                float gf = gp[64]      + gp[2048+64]   + gp[4096+64]   + gp[6144+64];
                float gg = gp[128]     + gp[2048+128]  + gp[4096+128]  + gp[6144+128];
                float go = gp[192]     + gp[2048+192]  + gp[4096+192]  + gp[6144+192];
                float nc = sigf(gf) * c1r + sigf(gi) * tanh_f(gg);
                c1r = nc;
                hn[j * 8 + b] = sigf(go) * tanh_f(nc);
            }
        } else {
            if (i >= 1) {
                int t2 = tid - 512;
                u64 a00, a01, a02, a03, a10, a11, a12, a13;
                if (sB == 0) { a00=a01=a02=a03=bvA; a10=a11=a12=a13=bvB; }
                else { a00=a01=a02=a03=a10=a11=a12=a13=0ULL; }
                const float* hk = hc + sB * 128;   // 16 rows per split
                #pragma unroll
                for (int c = 0; c < 16; c++) {
                    ulonglong2 hA = *(const ulonglong2*)&hk[c * 8];
                    ulonglong2 hB = *(const ulonglong2*)&hk[c * 8 + 4];
                    u64 w0 = pack2(wreg[c], wreg[c]);
                    a00 = fma2(w0, hA.x, a00); a01 = fma2(w0, hA.y, a01);
                    a02 = fma2(w0, hB.x, a02); a03 = fma2(w0, hB.y, a03);
                    u64 w1p = pack2(wreg[16 + c], wreg[16 + c]);
                    a10 = fma2(w1p, hA.x, a10); a11 = fma2(w1p, hA.y, a11);
                    a12 = fma2(w1p, hB.x, a12); a13 = fma2(w1p, hB.y, a13);
                }
                float f0, f1;
                float* gp0 = g2p + sB * 1024 + 2 * pB;
                unpack2(a00, f0, f1); gp0[0]   = f0; gp0[128] = f1;
                unpack2(a01, f0, f1); gp0[256] = f0; gp0[384] = f1;
                unpack2(a02, f0, f1); gp0[512] = f0; gp0[640] = f1;
                unpack2(a03, f0, f1); gp0[768] = f0; gp0[896] = f1;
                float* gp1 = gp0 + 1;
                unpack2(a10, f0, f1); gp1[0]   = f0; gp1[128] = f1;
                unpack2(a11, f0, f1); gp1[256] = f0; gp1[384] = f1;
                unpack2(a12, f0, f1); gp1[512] = f0; gp1[640] = f1;
                unpack2(a13, f0, f1); gp1[768] = f0; gp1[896] = f1;

                asm volatile("bar.sync 2, 384;" ::: "memory");

                // cell update: one cell per thread (first 256), sum 6 splits
                if (t2 < 256) {
                    int b = t2 >> 5, j = t2 & 31;
                    const float* gp = g2p + b * 128 + j;
                    float gi = 0.f, gf = 0.f, gg = 0.f, go = 0.f;
                    #pragma unroll
                    for (int s = 0; s < 6; s++) {
                        gi += gp[s * 1024];
                        gf += gp[s * 1024 + 32];
                        gg += gp[s * 1024 + 64];
                        go += gp[s * 1024 + 96];
                    }
                    float nc = sigf(gf) * c2r + sigf(gi) * tanh_f(gg);
                    c2r = nc;
                    hn[(64 + j) * 8 + b] = sigf(go) * tanh_f(nc);
                }
            }
        }
        __syncthreads();
    }

    // ---- qkv projection of l2_final = h2(15) + h1(15)[:32] ----
    if (tid < 768) {
        int b = tid / 96, g = tid % 96;
        float acc = attn_b[g];
        #pragma unroll 8
        for (int e = 0; e < 32; e++) {
            float vv = hcat[e * 8 + b] + hcat[768 + (64 + e) * 8 + b];
            acc = fmaf(vv, attn_w[g * 32 + e], acc);
        }
        int m = b0 + b;
        int head = (g & 31) >> 3;
        int d = g & 7;
        if (g < 32)      q_g[head * 8192 + m * 8 + d] = acc * 0.3535533905932738f;
        else if (g < 64) k_g[head * 8192 + m * 8 + d] = acc;
        else             v_g[head * 8192 + m * 8 + d] = acc;
    }
}

// =====================================================================
// Kernel 2: fused attention + MLP head, 128 CTAs x 512 thr, 8 rows each.
//   warp w: head = w&3, rowgroup rg = (w>>2)&1 (4 rows), keyhalf kh = w>>3.
//   Hot loop fully f32x2-packed: scores via (even,odd)-lane partial dots,
//   softmax*V via natural v pairs. k/v direct from L1/L2.
// =====================================================================
__global__ void __launch_bounds__(512, 1) attn_mlp_kernel(
    const float* __restrict__ ow, const float* __restrict__ ob,
    const float* __restrict__ d1w, const float* __restrict__ d1b,
    const float* __restrict__ bg1, const float* __restrict__ bb1,
    const float* __restrict__ d2w, const float* __restrict__ d2b,
    const float* __restrict__ bg2, const float* __restrict__ bb2,
    const float* __restrict__ d3w, const float* __restrict__ d3b,
    float* __restrict__ out)
{
    __shared__ float owT[1024], d1T[2048], d2T[2048], d3s[32];
    __shared__ float obs[32], d1bs[64], d2bs[32], s1v[64], sb1[64], s2v[32], sb2[32];
    __shared__ float part[2][8][4][12];   // [kh][row][head][8 acc + sum], padded
    __shared__ float att[8 * 32], z1[8 * 32], z2[8 * 64], z3[32 * 8];

    const int tid = threadIdx.x;
    const int lane = tid & 31, w = tid >> 5;
    const int r0 = blockIdx.x * 8;
    const float bnscale = rsqrtf(1.f + 1e-5f);

    // ---- stage MLP weights (512-thread strides) ----
    for (int i = tid; i < 1024; i += 512) { int o = i & 31, e = i >> 5; owT[e * 32 + o] = ow[o * 32 + e]; }
    for (int i = tid; i < 2048; i += 512) { int o = i & 63, e = i >> 6; d1T[e * 64 + o] = d1w[o * 32 + e]; }
    for (int i = tid; i < 2048; i += 512) { int o = i & 31, e = i >> 5; d2T[e * 32 + o] = d2w[o * 64 + e]; }
    if (tid < 32) { d3s[tid] = d3w[tid]; obs[tid] = ob[tid]; d2bs[tid] = d2b[tid]; s2v[tid] = bg2[tid] * bnscale; sb2[tid] = bb2[tid]; }
    if (tid < 64) { d1bs[tid] = d1b[tid]; s1v[tid] = bg1[tid] * bnscale; sb1[tid] = bb1[tid]; }

    // ---- attention partials: warp = (head, 4-row group, key-half) ----
    {
        const int head = w & 3;
        const int rg = (w >> 2) & 1;
        const int kh = w >> 3;
        const float* qbase = q_g + head * 8192 + (r0 + rg * 4) * 8;
        u64 qu[4][4];   // q row as 4 natural (even,odd) u64 pairs
        #pragma unroll
        for (int r = 0; r < 4; r++) {
            const ulonglong2* qp = (const ulonglong2*)(qbase + r * 8);
            ulonglong2 qv0 = qp[0], qv1 = qp[1];
            qu[r][0] = qv0.x; qu[r][1] = qv0.y;
            qu[r][2] = qv1.x; qu[r][3] = qv1.y;
        }

        const float* kg = k_g + head * 8192 + kh * 4096;
        const float* vg = v_g + head * 8192 + kh * 4096;

        float sums[4] = {0.f, 0.f, 0.f, 0.f};
        u64 acc2[4][4];
        #pragma unroll
        for (int r = 0; r < 4; r++)
            #pragma unroll
            for (int d = 0; d < 4; d++) acc2[r][d] = 0ULL;

        #pragma unroll 4
        for (int mi = 0; mi < 16; mi++) {
            int m = lane + mi * 32;
            const ulonglong2* kp = (const ulonglong2*)(kg + m * 8);
            ulonglong2 kv0 = kp[0], kv1 = kp[1];
            const ulonglong2* vp = (const ulonglong2*)(vg + m * 8);
            ulonglong2 vv0 = vp[0], vv1 = vp[1];
            #pragma unroll
            for (int r = 0; r < 4; r++) {
                // packed dot: lanes hold (sum of even d, sum of odd d)
                u64 s2 = fma2(qu[r][0], kv0.x, 0ULL);
                s2 = fma2(qu[r][1], kv0.y, s2);
                s2 = fma2(qu[r][2], kv1.x, s2);
                s2 = fma2(qu[r][3], kv1.y, s2);
                float se, so;
                unpack2(s2, se, so);
                float e = __expf(se + so);
                sums[r] += e;
                u64 e2 = pack2(e, e);
                acc2[r][0] = fma2(e2, vv0.x, acc2[r][0]);
                acc2[r][1] = fma2(e2, vv0.y, acc2[r][1]);
                acc2[r][2] = fma2(e2, vv1.x, acc2[r][2]);
                acc2[r][3] = fma2(e2, vv1.y, acc2[r][3]);
            }
        }
        // butterfly reduce across the warp (packed adds)
        #pragma unroll
        for (int o = 16; o > 0; o >>= 1) {
            #pragma unroll
            for (int r = 0; r < 4; r++) {
                sums[r] += __shfl_xor_sync(0xffffffffu, sums[r], o);
                #pragma unroll
                for (int d = 0; d < 4; d++)
                    acc2[r][d] = add2(acc2[r][d],
                                      __shfl_xor_sync(0xffffffffu, acc2[r][d], o));
            }
        }
        if (lane < 4) {
            int row = rg * 4 + lane;
            float* pp = &part[kh][row][head][0];
            #pragma unroll
            for (int d = 0; d < 4; d++) {
                float f0, f1;
                unpack2(acc2[lane][d], f0, f1);
                pp[2 * d] = f0; pp[2 * d + 1] = f1;
            }
            pp[8] = sums[lane];
        }
    }
    __syncthreads();

    // ---- combine halves: att[b][e] ----
    if (tid < 256) {
        int b = tid >> 5, e = tid & 31;
        int head = e >> 3, d = e & 7;
        float a = part[0][b][head][d] + part[1][b][head][d];
        float s = part[0][b][head][8] + part[1][b][head][8];
        att[b * 32 + e] = a / s;
    }
    __syncthreads();

    // ---- attention output projection: 8x32 = 256 outputs ----
    if (tid < 256) {
        int b = tid >> 5, o = tid & 31;
        float a = obs[o];
        #pragma unroll 8
        for (int e = 0; e < 32; e++) a += att[b * 32 + e] * owT[e * 32 + o];
        z1[b * 32 + o] = a;
    }
    __syncthreads();

    // ---- dense1 + bn1 + relu: 8x64 = 512 outputs ----
    {
        int b = tid >> 6, o = tid & 63;
        float a = d1bs[o];
        #pragma unroll 8
        for (int e = 0; e < 32; e++) a += z1[b * 32 + e] * d1T[e * 64 + o];
        a = a * s1v[o] + sb1[o];
        z2[b * 64 + o] = fmaxf(a, 0.f);
    }
    __syncthreads();

    // ---- dense2 + bn2 + relu: 8x32 (store transposed [o][b]) ----
    if (tid < 256) {
        int b = tid >> 5, o = tid & 31;
        float a = d2bs[o];
        #pragma unroll 8
        for (int e = 0; e < 64; e++) a += z2[b * 64 + e] * d2T[e * 32 + o];
        a = a * s2v[o] + sb2[o];
        z3[o * 8 + b] = fmaxf(a, 0.f);
    }
    __syncthreads();

    // ---- dense3 + sigmoid ----
    if (tid < 8) {
        int b = tid;
        float a = d3b[0];
        #pragma unroll 8
        for (int e = 0; e < 32; e++) a += z3[e * 8 + b] * d3s[e];
        out[r0 + b] = 1.f / (1.f + __expf(-a));
    }
}

// =====================================================================
extern "C" void kernel_launch(void* const* d_in, const int* in_sizes, int n_in,
                              void* d_out, int out_size)
{
    const float* x      = (const float*)d_in[0];
    const float* emb_w  = (const float*)d_in[1];
    const float* emb_b  = (const float*)d_in[2];
    const float* l1_wih = (const float*)d_in[3];
    const float* l1_whh = (const float*)d_in[4];
    const float* l1_bih = (const float*)d_in[5];
    const float* l1_bhh = (const float*)d_in[6];
    const float* l2_wih = (const float*)d_in[7];
    const float* l2_whh = (const float*)d_in[8];
    const float* l2_bih = (const float*)d_in[9];
    const float* l2_bhh = (const float*)d_in[10];
    const float* attn_w = (const float*)d_in[11];
    const float* attn_b = (const float*)d_in[12];
    const float* attn_ow = (const float*)d_in[13];
    const float* attn_ob = (const float*)d_in[14];
    const float* d1_w   = (const float*)d_in[15];
    const float* d1_b   = (const float*)d_in[16];
    const float* bn1_g  = (const float*)d_in[17];
    const float* bn1_b  = (const float*)d_in[18];
    const float* d2_w   = (const float*)d_in[19];
    const float* d2_b   = (const float*)d_in[20];
    const float* bn2_g  = (const float*)d_in[21];
    const float* bn2_b  = (const float*)d_in[22];
    const float* d3_w   = (const float*)d_in[23];
    const float* d3_b   = (const float*)d_in[24];
    float* out = (float*)d_out;

    const int smem1 = 20672 * 4;   // 82,688 B
    cudaFuncSetAttribute(lstm_kernel, cudaFuncAttributeMaxDynamicSharedMemorySize, smem1);

    lstm_kernel<<<128, 896, smem1>>>(x, emb_w, emb_b,
                                     l1_wih, l1_whh, l1_bih, l1_bhh,
                                     l2_wih, l2_whh, l2_bih, l2_bhh,
                                     attn_w, attn_b);
    attn_mlp_kernel<<<128, 512>>>(attn_ow, attn_ob, d1_w, d1_b,
                                  bn1_g, bn1_b, d2_w, d2_b,
                                  bn2_g, bn2_b, d3_w, d3_b, out);
}

// round 15
// speedup vs baseline: 1.0090x; 1.0090x over previous
#include <cuda_runtime.h>
#include <math.h>

// ---------------- global scratch (no allocations allowed) ----------------
__device__ float q_g[4 * 1024 * 8];
__device__ float k_g[4 * 1024 * 8];
__device__ float v_g[4 * 1024 * 8];

typedef unsigned long long u64;

__device__ __forceinline__ float tanh_f(float x) {
    float y; asm("tanh.approx.f32 %0, %1;" : "=f"(y) : "f"(x)); return y;
}
__device__ __forceinline__ float sigf(float x) {
    return fmaf(0.5f, tanh_f(0.5f * x), 0.5f);
}
__device__ __forceinline__ u64 pack2(float a, float b) {
    u64 r; asm("mov.b64 %0, {%1,%2};" : "=l"(r) : "f"(a), "f"(b)); return r;
}
__device__ __forceinline__ void unpack2(u64 v, float& a, float& b) {
    asm("mov.b64 {%0,%1}, %2;" : "=f"(a), "=f"(b) : "l"(v));
}
__device__ __forceinline__ u64 fma2(u64 a, u64 b, u64 c) {
    u64 d; asm("fma.rn.f32x2 %0, %1, %2, %3;" : "=l"(d) : "l"(a), "l"(b), "l"(c)); return d;
}

// =====================================================================
// Kernel 1: pipelined LSTM1 + LSTM2, balanced 16-iter GEMVs.
//   vs round-13: the x/emb-fold term of LSTM1 gates is applied in the
//   CELL phase (uniform GEMV across all 4 k-quarters; quarter-0 tail
//   removed from the barrier-critical path).
// =====================================================================
__global__ void __launch_bounds__(896, 1) lstm_kernel(
    const float* __restrict__ x,
    const float* __restrict__ emb_w, const float* __restrict__ emb_b,
    const float* __restrict__ w1, const float* __restrict__ u1,
    const float* __restrict__ b1i, const float* __restrict__ b1h,
    const float* __restrict__ w2, const float* __restrict__ u2,
    const float* __restrict__ b2i, const float* __restrict__ b2h,
    const float* __restrict__ attn_w, const float* __restrict__ attn_b)
{
    extern __shared__ __align__(16) float sm[];
    float* g1p    = sm;              // [4][8][256]  8192
    float* g2p    = g1p + 8192;     // [6][8][128]  6144
    float* pt1s   = g2p + 6144;     // [16][256]    4096
    float* pe     = pt1s + 4096;    // [16][32]      512
    float* xs     = pe + 512;       // [16][8]       128
    float* hcat   = xs + 128;       // [2][96][8]   1536
    float* embw_s = hcat + 1536;    // 32
    float* embb_s = embw_s + 32;    // 32
    float* we1s   = embb_s + 32;    // 256

    const int tid = threadIdx.x;
    const int b0 = blockIdx.x * 8;

    // ---- shared prologue ----
    if (tid < 512) {
        int t = tid >> 5, e = tid & 31;
        int half = e >> 1;
        float div = __expf(-(float)(2 * half) * (9.210340371976184f / 32.0f));
        float arg = (float)t * div;
        pe[tid] = (e & 1) ? __cosf(arg) : __sinf(arg);
    }
    if (tid < 32) { embw_s[tid] = emb_w[tid]; embb_s[tid] = emb_b[tid]; }
    if (tid < 128) { int t = tid >> 3, b = tid & 7; xs[tid] = x[(b0 + b) * 16 + t]; }
    for (int i = tid; i < 1536; i += 896) hcat[i] = 0.f;
    __syncthreads();

    // ---- pt1s + we1 (embedding folded into LSTM1): threads < 256 ----
    if (tid < 256) {
        int gate = 2 * (tid & 127) + (tid >> 7);
        float w1r[32];
        const float4* w1p = (const float4*)(w1 + gate * 32);
        #pragma unroll
        for (int qq = 0; qq < 8; qq++) {
            float4 v = w1p[qq];
            w1r[qq*4+0]=v.x; w1r[qq*4+1]=v.y; w1r[qq*4+2]=v.z; w1r[qq*4+3]=v.w;
        }
        float we1 = 0.f, wb = b1i[gate] + b1h[gate];
        #pragma unroll
        for (int e = 0; e < 32; e++) {
            we1 = fmaf(w1r[e], embw_s[e], we1);
            wb  = fmaf(w1r[e], embb_s[e], wb);
        }
        we1s[gate] = we1;
        #pragma unroll
        for (int t = 0; t < 16; t++) {
            float s = wb;
            #pragma unroll
            for (int e = 0; e < 32; e++) s = fmaf(w1r[e], pe[t * 32 + e], s);
            pt1s[t * 256 + gate] = s;
        }
    }
    __syncthreads();

    // ---- per-thread register setup ----
    float wreg[32];
    float wx0 = 0.f, wx1 = 0.f, wx2 = 0.f, wx3 = 0.f;   // A cell: we1 of my 4 gates
    u64 bvA = 0, bvB = 0;
    float c1r = 0.f, c2r = 0.f;
    int pA = 0, qA = 0, pB = 0, sB = 0;

    if (tid < 512) {
        pA = tid & 127; qA = tid >> 7;
        const float4* a0 = (const float4*)(u1 + (2 * pA) * 64 + qA * 16);
        const float4* a1 = (const float4*)(u1 + (2 * pA + 1) * 64 + qA * 16);
        #pragma unroll
        for (int qq = 0; qq < 4; qq++) {
            float4 v = a0[qq];
            wreg[qq*4+0]=v.x; wreg[qq*4+1]=v.y; wreg[qq*4+2]=v.z; wreg[qq*4+3]=v.w;
            float4 u = a1[qq];
            wreg[16+qq*4+0]=u.x; wreg[16+qq*4+1]=u.y; wreg[16+qq*4+2]=u.z; wreg[16+qq*4+3]=u.w;
        }
        // cell role: j = tid & 63 -> gates j, 64+j, 128+j, 192+j
        int j = tid & 63;
        wx0 = we1s[j]; wx1 = we1s[64 + j]; wx2 = we1s[128 + j]; wx3 = we1s[192 + j];
    } else {
        int t2 = tid - 512;
        pB = t2 & 63; sB = t2 >> 6;   // sB in [0,6)
        #pragma unroll
        for (int g = 0; g < 2; g++) {
            int row = 2 * pB + g;
            const float4* p = (sB < 4)
                ? (const float4*)(w2 + row * 64 + sB * 16)
                : (const float4*)(u2 + row * 32 + (sB - 4) * 16);
            #pragma unroll
            for (int qq = 0; qq < 4; qq++) {
                float4 v = p[qq];
                wreg[g*16+qq*4+0]=v.x; wreg[g*16+qq*4+1]=v.y;
                wreg[g*16+qq*4+2]=v.z; wreg[g*16+qq*4+3]=v.w;
            }
        }
        if (sB == 0) {
            float ba = b2i[2 * pB] + b2h[2 * pB];
            float bb = b2i[2 * pB + 1] + b2h[2 * pB + 1];
            bvA = pack2(ba, ba); bvB = pack2(bb, bb);
        }
    }
    __syncthreads();

    // ---- pipelined main loop: 17 iterations ----
    for (int i = 0; i < 17; ++i) {
        int cur = i & 1;
        const float* hc = hcat + cur * 768;
        float* hn = hcat + (cur ^ 1) * 768;
        if (tid < 512) {
            if (i < 16) {
                // uniform GEMV across all quarters (x/pt folded in cell phase)
                u64 a00 = 0, a01 = 0, a02 = 0, a03 = 0,
                    a10 = 0, a11 = 0, a12 = 0, a13 = 0;
                const float* hk = hc + qA * 128;
                #pragma unroll
                for (int k = 0; k < 16; k++) {
                    ulonglong2 hA = *(const ulonglong2*)&hk[k * 8];
                    ulonglong2 hB = *(const ulonglong2*)&hk[k * 8 + 4];
                    u64 w0 = pack2(wreg[k], wreg[k]);
                    a00 = fma2(w0, hA.x, a00); a01 = fma2(w0, hA.y, a01);
                    a02 = fma2(w0, hB.x, a02); a03 = fma2(w0, hB.y, a03);
                    u64 w1p = pack2(wreg[16 + k], wreg[16 + k]);
                    a10 = fma2(w1p, hA.x, a10); a11 = fma2(w1p, hA.y, a11);
                    a12 = fma2(w1p, hB.x, a12); a13 = fma2(w1p, hB.y, a13);
                }
                float f0, f1;
                float* gp0 = g1p + qA * 2048 + 2 * pA;
                unpack2(a00, f0, f1); gp0[0]    = f0; gp0[256]  = f1;
                unpack2(a01, f0, f1); gp0[512]  = f0; gp0[768]  = f1;
                unpack2(a02, f0, f1); gp0[1024] = f0; gp0[1280] = f1;
                unpack2(a03, f0, f1); gp0[1536] = f0; gp0[1792] = f1;
                float* gp1 = gp0 + 1;
                unpack2(a10, f0, f1); gp1[0]    = f0; gp1[256]  = f1;
                unpack2(a11, f0, f1); gp1[512]  = f0; gp1[768]  = f1;
                unpack2(a12, f0, f1); gp1[1024] = f0; gp1[1280] = f1;
                unpack2(a13, f0, f1); gp1[1536] = f0; gp1[1792] = f1;

                asm volatile("bar.sync 1, 512;" ::: "memory");

                // cell update: one cell per thread, sum 4 quarters + x/pt fold
                int b = tid >> 6, j = tid & 63;
                const float* gp = g1p + b * 256 + j;
                float xv = xs[i * 8 + b];
                const float* pt = pt1s + i * 256 + j;
                float gi = gp[0]       + gp[2048]      + gp[4096]      + gp[6144];
                float gf = gp[64]      + gp[2048+64]   + gp[4096+64]   + gp[6144+64];
                float gg = gp[128]     + gp[2048+128]  + gp[4096+128]  + gp[6144+128];
                float go = gp[192]     + gp[2048+192]  + gp[4096+192]  + gp[6144+192];
                gi += fmaf(wx0, xv, pt[0]);
                gf += fmaf(wx1, xv, pt[64]);
                gg += fmaf(wx2, xv, pt[128]);
                go += fmaf(wx3, xv, pt[192]);
                float nc = sigf(gf) * c1r + sigf(gi) * tanh_f(gg);
                c1r = nc;
                hn[j * 8 + b] = sigf(go) * tanh_f(nc);
            }
        } else {
            if (i >= 1) {
                int t2 = tid - 512;
                u64 a00, a01, a02, a03, a10, a11, a12, a13;
                if (sB == 0) { a00=a01=a02=a03=bvA; a10=a11=a12=a13=bvB; }
                else { a00=a01=a02=a03=a10=a11=a12=a13=0ULL; }
                const float* hk = hc + sB * 128;   // 16 rows per split
                #pragma unroll
                for (int c = 0; c < 16; c++) {
                    ulonglong2 hA = *(const ulonglong2*)&hk[c * 8];
                    ulonglong2 hB = *(const ulonglong2*)&hk[c * 8 + 4];
                    u64 w0 = pack2(wreg[c], wreg[c]);
                    a00 = fma2(w0, hA.x, a00); a01 = fma2(w0, hA.y, a01);
                    a02 = fma2(w0, hB.x, a02); a03 = fma2(w0, hB.y, a03);
                    u64 w1p = pack2(wreg[16 + c], wreg[16 + c]);
                    a10 = fma2(w1p, hA.x, a10); a11 = fma2(w1p, hA.y, a11);
                    a12 = fma2(w1p, hB.x, a12); a13 = fma2(w1p, hB.y, a13);
                }
                float f0, f1;
                float* gp0 = g2p + sB * 1024 + 2 * pB;
                unpack2(a00, f0, f1); gp0[0]   = f0; gp0[128] = f1;
                unpack2(a01, f0, f1); gp0[256] = f0; gp0[384] = f1;
                unpack2(a02, f0, f1); gp0[512] = f0; gp0[640] = f1;
                unpack2(a03, f0, f1); gp0[768] = f0; gp0[896] = f1;
                float* gp1 = gp0 + 1;
                unpack2(a10, f0, f1); gp1[0]   = f0; gp1[128] = f1;
                unpack2(a11, f0, f1); gp1[256] = f0; gp1[384] = f1;
                unpack2(a12, f0, f1); gp1[512] = f0; gp1[640] = f1;
                unpack2(a13, f0, f1); gp1[768] = f0; gp1[896] = f1;

                asm volatile("bar.sync 2, 384;" ::: "memory");

                // cell update: one cell per thread (first 256), sum 6 splits
                if (t2 < 256) {
                    int b = t2 >> 5, j = t2 & 31;
                    const float* gp = g2p + b * 128 + j;
                    float gi = 0.f, gf = 0.f, gg = 0.f, go = 0.f;
                    #pragma unroll
                    for (int s = 0; s < 6; s++) {
                        gi += gp[s * 1024];
                        gf += gp[s * 1024 + 32];
                        gg += gp[s * 1024 + 64];
                        go += gp[s * 1024 + 96];
                    }
                    float nc = sigf(gf) * c2r + sigf(gi) * tanh_f(gg);
                    c2r = nc;
                    hn[(64 + j) * 8 + b] = sigf(go) * tanh_f(nc);
                }
            }
        }
        __syncthreads();
    }

    // ---- qkv projection of l2_final = h2(15) + h1(15)[:32] ----
    if (tid < 768) {
        int b = tid / 96, g = tid % 96;
        float acc = attn_b[g];
        #pragma unroll 8
        for (int e = 0; e < 32; e++) {
            float vv = hcat[e * 8 + b] + hcat[768 + (64 + e) * 8 + b];
            acc = fmaf(vv, attn_w[g * 32 + e], acc);
        }
        int m = b0 + b;
        int head = (g & 31) >> 3;
        int d = g & 7;
        if (g < 32)      q_g[head * 8192 + m * 8 + d] = acc * 0.3535533905932738f;
        else if (g < 64) k_g[head * 8192 + m * 8 + d] = acc;
        else             v_g[head * 8192 + m * 8 + d] = acc;
    }
}

// =====================================================================
// Kernel 2: fused attention + MLP head, 128 CTAs x 512 thr, 8 rows each.
//   (byte-identical to the round-13 best: scalar float4 loop, unroll 4)
// =====================================================================
__global__ void __launch_bounds__(512, 1) attn_mlp_kernel(
    const float* __restrict__ ow, const float* __restrict__ ob,
    const float* __restrict__ d1w, const float* __restrict__ d1b,
    const float* __restrict__ bg1, const float* __restrict__ bb1,
    const float* __restrict__ d2w, const float* __restrict__ d2b,
    const float* __restrict__ bg2, const float* __restrict__ bb2,
    const float* __restrict__ d3w, const float* __restrict__ d3b,
    float* __restrict__ out)
{
    __shared__ float owT[1024], d1T[2048], d2T[2048], d3s[32];
    __shared__ float obs[32], d1bs[64], d2bs[32], s1v[64], sb1[64], s2v[32], sb2[32];
    __shared__ float part[2][8][4][12];   // [kh][row][head][8 acc + sum], padded
    __shared__ float att[8 * 32], z1[8 * 32], z2[8 * 64], z3[32 * 8];

    const int tid = threadIdx.x;
    const int lane = tid & 31, w = tid >> 5;
    const int r0 = blockIdx.x * 8;
    const float bnscale = rsqrtf(1.f + 1e-5f);

    // ---- stage MLP weights (512-thread strides) ----
    for (int i = tid; i < 1024; i += 512) { int o = i & 31, e = i >> 5; owT[e * 32 + o] = ow[o * 32 + e]; }
    for (int i = tid; i < 2048; i += 512) { int o = i & 63, e = i >> 6; d1T[e * 64 + o] = d1w[o * 32 + e]; }
    for (int i = tid; i < 2048; i += 512) { int o = i & 31, e = i >> 5; d2T[e * 32 + o] = d2w[o * 64 + e]; }
    if (tid < 32) { d3s[tid] = d3w[tid]; obs[tid] = ob[tid]; d2bs[tid] = d2b[tid]; s2v[tid] = bg2[tid] * bnscale; sb2[tid] = bb2[tid]; }
    if (tid < 64) { d1bs[tid] = d1b[tid]; s1v[tid] = bg1[tid] * bnscale; sb1[tid] = bb1[tid]; }

    // ---- attention partials: warp = (head, 4-row group, key-half) ----
    {
        const int head = w & 3;
        const int rg = (w >> 2) & 1;
        const int kh = w >> 3;
        const float* qbase = q_g + head * 8192 + (r0 + rg * 4) * 8;
        float4 qa[4], qb[4];
        #pragma unroll
        for (int r = 0; r < 4; r++) {
            const float4* qp = (const float4*)(qbase + r * 8);
            qa[r] = qp[0]; qb[r] = qp[1];
        }

        const float4* kg = (const float4*)(k_g + head * 8192 + kh * 4096);
        const float4* vg = (const float4*)(v_g + head * 8192 + kh * 4096);

        float sums[4] = {0.f, 0.f, 0.f, 0.f};
        float acc[4][8];
        #pragma unroll
        for (int r = 0; r < 4; r++)
            #pragma unroll
            for (int d = 0; d < 8; d++) acc[r][d] = 0.f;

        #pragma unroll 4
        for (int mi = 0; mi < 16; mi++) {
            int m = lane + mi * 32;
            float4 ka = kg[m * 2], kb = kg[m * 2 + 1];
            float4 va = vg[m * 2], vb = vg[m * 2 + 1];
            #pragma unroll
            for (int r = 0; r < 4; r++) {
                float s = qa[r].x * ka.x;
                s = fmaf(qa[r].y, ka.y, s);
                s = fmaf(qa[r].z, ka.z, s);
                s = fmaf(qa[r].w, ka.w, s);
                s = fmaf(qb[r].x, kb.x, s);
                s = fmaf(qb[r].y, kb.y, s);
                s = fmaf(qb[r].z, kb.z, s);
                s = fmaf(qb[r].w, kb.w, s);
                float e = __expf(s);
                sums[r] += e;
                acc[r][0] = fmaf(e, va.x, acc[r][0]);
                acc[r][1] = fmaf(e, va.y, acc[r][1]);
                acc[r][2] = fmaf(e, va.z, acc[r][2]);
                acc[r][3] = fmaf(e, va.w, acc[r][3]);
                acc[r][4] = fmaf(e, vb.x, acc[r][4]);
                acc[r][5] = fmaf(e, vb.y, acc[r][5]);
                acc[r][6] = fmaf(e, vb.z, acc[r][6]);
                acc[r][7] = fmaf(e, vb.w, acc[r][7]);
            }
        }
        // butterfly reduce across the warp
        #pragma unroll
        for (int o = 16; o > 0; o >>= 1) {
            #pragma unroll
            for (int r = 0; r < 4; r++) {
                sums[r] += __shfl_xor_sync(0xffffffffu, sums[r], o);
                #pragma unroll
                for (int d = 0; d < 8; d++)
                    acc[r][d] += __shfl_xor_sync(0xffffffffu, acc[r][d], o);
            }
        }
        if (lane < 4) {
            int row = rg * 4 + lane;
            float* pp = &part[kh][row][head][0];
            #pragma unroll
            for (int d = 0; d < 8; d++) pp[d] = acc[lane][d];
            pp[8] = sums[lane];
        }
    }
    __syncthreads();

    // ---- combine halves: att[b][e] ----
    if (tid < 256) {
        int b = tid >> 5, e = tid & 31;
        int head = e >> 3, d = e & 7;
        float a = part[0][b][head][d] + part[1][b][head][d];
        float s = part[0][b][head][8] + part[1][b][head][8];
        att[b * 32 + e] = a / s;
    }
    __syncthreads();

    // ---- attention output projection: 8x32 = 256 outputs ----
    if (tid < 256) {
        int b = tid >> 5, o = tid & 31;
        float a = obs[o];
        #pragma unroll 8
        for (int e = 0; e < 32; e++) a += att[b * 32 + e] * owT[e * 32 + o];
        z1[b * 32 + o] = a;
    }
    __syncthreads();

    // ---- dense1 + bn1 + relu: 8x64 = 512 outputs ----
    {
        int b = tid >> 6, o = tid & 63;
        float a = d1bs[o];
        #pragma unroll 8
        for (int e = 0; e < 32; e++) a += z1[b * 32 + e] * d1T[e * 64 + o];
        a = a * s1v[o] + sb1[o];
        z2[b * 64 + o] = fmaxf(a, 0.f);
    }
    __syncthreads();

    // ---- dense2 + bn2 + relu: 8x32 (store transposed [o][b]) ----
    if (tid < 256) {
        int b = tid >> 5, o = tid & 31;
        float a = d2bs[o];
        #pragma unroll 8
        for (int e = 0; e < 64; e++) a += z2[b * 64 + e] * d2T[e * 32 + o];
        a = a * s2v[o] + sb2[o];
        z3[o * 8 + b] = fmaxf(a, 0.f);
    }
    __syncthreads();

    // ---- dense3 + sigmoid ----
    if (tid < 8) {
        int b = tid;
        float a = d3b[0];
        #pragma unroll 8
        for (int e = 0; e < 32; e++) a += z3[e * 8 + b] * d3s[e];
        out[r0 + b] = 1.f / (1.f + __expf(-a));
    }
}

// =====================================================================
extern "C" void kernel_launch(void* const* d_in, const int* in_sizes, int n_in,
                              void* d_out, int out_size)
{
    const float* x      = (const float*)d_in[0];
    const float* emb_w  = (const float*)d_in[1];
    const float* emb_b  = (const float*)d_in[2];
    const float* l1_wih = (const float*)d_in[3];
    const float* l1_whh = (const float*)d_in[4];
    const float* l1_bih = (const float*)d_in[5];
    const float* l1_bhh = (const float*)d_in[6];
    const float* l2_wih = (const float*)d_in[7];
    const float* l2_whh = (const float*)d_in[8];
    const float* l2_bih = (const float*)d_in[9];
    const float* l2_bhh = (const float*)d_in[10];
    const float* attn_w = (const float*)d_in[11];
    const float* attn_b = (const float*)d_in[12];
    const float* attn_ow = (const float*)d_in[13];
    const float* attn_ob = (const float*)d_in[14];
    const float* d1_w   = (const float*)d_in[15];
    const float* d1_b   = (const float*)d_in[16];
    const float* bn1_g  = (const float*)d_in[17];
    const float* bn1_b  = (const float*)d_in[18];
    const float* d2_w   = (const float*)d_in[19];
    const float* d2_b   = (const float*)d_in[20];
    const float* bn2_g  = (const float*)d_in[21];
    const float* bn2_b  = (const float*)d_in[22];
    const float* d3_w   = (const float*)d_in[23];
    const float* d3_b   = (const float*)d_in[24];
    float* out = (float*)d_out;

    const int smem1 = 20928 * 4;   // 83,712 B
    cudaFuncSetAttribute(lstm_kernel, cudaFuncAttributeMaxDynamicSharedMemorySize, smem1);

    lstm_kernel<<<128, 896, smem1>>>(x, emb_w, emb_b,
                                     l1_wih, l1_whh, l1_bih, l1_bhh,
                                     l2_wih, l2_whh, l2_bih, l2_bhh,
                                     attn_w, attn_b);
    attn_mlp_kernel<<<128, 512>>>(attn_ow, attn_ob, d1_w, d1_b,
                                  bn1_g, bn1_b, d2_w, d2_b,
                                  bn2_g, bn2_b, d3_w, d3_b, out);
}